// round 6
// baseline (speedup 1.0000x reference)
#include <cuda_runtime.h>
#include <cuda_bf16.h>

#define NN 8192
#define IN_DIM 256
#define HID 16
#define KNB 6

#define TPB_TOPK 128
#define WARPS_TOPK 4
#define ROWS_PER_WARP 4
#define ROWS_PER_BLOCK (WARPS_TOPK * ROWS_PER_WARP)
#define COL_SPLIT 2
#define COLS_PER_SPLIT (NN / COL_SPLIT)   // 4096
#define CT 512
#define SH_STRIDE 20  // floats per column (padded; LDS.128 conflict-free)

__device__ float g_h[NN * HID];
__device__ float g_rowsum[NN];
__device__ int   g_topk_idx[NN * KNB];
__device__ float g_topk_val[NN * KNB];
__device__ float g_part_val[NN * COL_SPLIT * KNB];
__device__ int   g_part_idx[NN * COL_SPLIT * KNB];

// ---------------------------------------------------------------------------
// K0: streaming zero-fill (evict-first stores; keeps g_h L2-resident)
// ---------------------------------------------------------------------------
__global__ __launch_bounds__(256) void k_zero(float4* __restrict__ out4) {
    const size_t total = (size_t)NN * NN / 4;
    size_t stride = (size_t)gridDim.x * blockDim.x;
    float4 z = make_float4(0.f, 0.f, 0.f, 0.f);
    for (size_t i = (size_t)blockIdx.x * blockDim.x + threadIdx.x; i < total; i += stride)
        __stcs(&out4[i], z);
}

__global__ void k_nop1(void) {}

// ---------------------------------------------------------------------------
// K1: warp-per-row h = normalize(x @ W^T + b); also zeroes rowsum.
// ---------------------------------------------------------------------------
__global__ __launch_bounds__(256) void k_embed(const float* __restrict__ x,
                                               const float* __restrict__ W,
                                               const float* __restrict__ b) {
    __shared__ float sW[HID * IN_DIM];
    for (int t = threadIdx.x; t < HID * IN_DIM / 4; t += blockDim.x)
        ((float4*)sW)[t] = ((const float4*)W)[t];
    __syncthreads();

    int warp = threadIdx.x >> 5;
    int lane = threadIdx.x & 31;
    int row = blockIdx.x * 8 + warp;

    float acc[HID];
#pragma unroll
    for (int d = 0; d < HID; d++) acc[d] = 0.0f;

    const float* xr = x + (size_t)row * IN_DIM;
#pragma unroll
    for (int q = 0; q < 8; q++) {
        float xv = xr[lane + 32 * q];
#pragma unroll
        for (int d = 0; d < HID; d++)
            acc[d] = fmaf(xv, sW[d * IN_DIM + lane + 32 * q], acc[d]);
    }

#pragma unroll
    for (int d = 0; d < HID; d++)
        acc[d] += __shfl_xor_sync(0xFFFFFFFFu, acc[d], 16);
#pragma unroll
    for (int d = 0; d < 8; d++) {
        bool hi = (lane & 8);
        float keep = hi ? acc[d + 8] : acc[d];
        float send = hi ? acc[d] : acc[d + 8];
        acc[d] = keep + __shfl_xor_sync(0xFFFFFFFFu, send, 8);
    }
#pragma unroll
    for (int d = 0; d < 4; d++) {
        bool hi = (lane & 4);
        float keep = hi ? acc[d + 4] : acc[d];
        float send = hi ? acc[d] : acc[d + 4];
        acc[d] = keep + __shfl_xor_sync(0xFFFFFFFFu, send, 4);
    }
#pragma unroll
    for (int d = 0; d < 2; d++) {
        bool hi = (lane & 2);
        float keep = hi ? acc[d + 2] : acc[d];
        float send = hi ? acc[d] : acc[d + 2];
        acc[d] = keep + __shfl_xor_sync(0xFFFFFFFFu, send, 2);
    }
    {
        bool hi = (lane & 1);
        float keep = hi ? acc[1] : acc[0];
        float send = hi ? acc[0] : acc[1];
        acc[0] = keep + __shfl_xor_sync(0xFFFFFFFFu, send, 1);
    }
    float val = acc[0] + b[lane & 15];

    float ss = val * val;
#pragma unroll
    for (int off = 1; off < 16; off <<= 1)
        ss += __shfl_xor_sync(0xFFFFFFFFu, ss, off);

    float inv = 1.0f / fmaxf(sqrtf(ss), 1e-12f);
    if (lane < 16) g_h[row * HID + lane] = val * inv;
    if (lane == 16) g_rowsum[row] = 0.0f;
}

// ---------------------------------------------------------------------------
__device__ __forceinline__ void insert6(float* v, int* ix, float s, int c) {
    float cv = s; int ci = c;
#pragma unroll
    for (int k = 0; k < KNB; k++) {
        bool gt = (cv > v[k]);
        float tv = v[k]; int ti = ix[k];
        if (gt) { v[k] = cv; ix[k] = ci; cv = tv; ci = ti; }
    }
}

// ---------------------------------------------------------------------------
// K2: column-split streaming top-6. block = (row-group, col-half).
// Writes partial top-6 lists; no atomics.
// ---------------------------------------------------------------------------
__global__ __launch_bounds__(TPB_TOPK) void k_topk(void) {
    __shared__ float sh[CT * SH_STRIDE];  // 40 KB

    int split = blockIdx.x & (COL_SPLIT - 1);
    int rgrp  = blockIdx.x >> 1;
    int warp = threadIdx.x >> 5;
    int lane = threadIdx.x & 31;
    int rbase = rgrp * ROWS_PER_BLOCK + warp * ROWS_PER_WARP;

    float hr[ROWS_PER_WARP][HID];
#pragma unroll
    for (int r = 0; r < ROWS_PER_WARP; r++)
#pragma unroll
        for (int d = 0; d < HID; d++)
            hr[r][d] = g_h[(size_t)(rbase + r) * HID + d];

    float v[ROWS_PER_WARP][KNB];
    int   ix[ROWS_PER_WARP][KNB];
#pragma unroll
    for (int r = 0; r < ROWS_PER_WARP; r++)
#pragma unroll
        for (int k = 0; k < KNB; k++) { v[r][k] = -2.0f; ix[r][k] = 0x7FFFFFFF; }

    const int NT = COLS_PER_SPLIT / CT;  // 8
    for (int tile = 0; tile < NT; tile++) {
        int cbase = split * COLS_PER_SPLIT + tile * CT;
        __syncthreads();
        for (int t = threadIdx.x; t < CT * (HID / 4); t += TPB_TOPK) {
            int c = t >> 2;
            int q = t & 3;
            float4 val = ((const float4*)g_h)[(size_t)(cbase + c) * (HID / 4) + q];
            *((float4*)&sh[c * SH_STRIDE + q * 4]) = val;
        }
        __syncthreads();

        for (int cc = lane; cc < CT; cc += 32) {
            int c = cbase + cc;
            const float4* f4 = (const float4*)&sh[cc * SH_STRIDE];
            float4 a0 = f4[0], a1 = f4[1], a2 = f4[2], a3 = f4[3];

            float s[ROWS_PER_WARP];
#pragma unroll
            for (int r = 0; r < ROWS_PER_WARP; r++) {
                float t0 = 0.f;
                t0 = fmaf(a0.x, hr[r][0],  t0);
                t0 = fmaf(a0.y, hr[r][1],  t0);
                t0 = fmaf(a0.z, hr[r][2],  t0);
                t0 = fmaf(a0.w, hr[r][3],  t0);
                t0 = fmaf(a1.x, hr[r][4],  t0);
                t0 = fmaf(a1.y, hr[r][5],  t0);
                t0 = fmaf(a1.z, hr[r][6],  t0);
                t0 = fmaf(a1.w, hr[r][7],  t0);
                t0 = fmaf(a2.x, hr[r][8],  t0);
                t0 = fmaf(a2.y, hr[r][9],  t0);
                t0 = fmaf(a2.z, hr[r][10], t0);
                t0 = fmaf(a2.w, hr[r][11], t0);
                t0 = fmaf(a3.x, hr[r][12], t0);
                t0 = fmaf(a3.y, hr[r][13], t0);
                t0 = fmaf(a3.z, hr[r][14], t0);
                t0 = fmaf(a3.w, hr[r][15], t0);
                s[r] = t0;
            }
            if (c != rbase + 0 && s[0] > v[0][KNB - 1]) insert6(v[0], ix[0], s[0], c);
            if (c != rbase + 1 && s[1] > v[1][KNB - 1]) insert6(v[1], ix[1], s[1], c);
            if (c != rbase + 2 && s[2] > v[2][KNB - 1]) insert6(v[2], ix[2], s[2], c);
            if (c != rbase + 3 && s[3] > v[3][KNB - 1]) insert6(v[3], ix[3], s[3], c);
        }
    }

    // merge lanes' top-6 per row -> partial list for this split
#pragma unroll
    for (int r = 0; r < ROWS_PER_WARP; r++) {
        int row = rbase + r;
        int ptr = 0;
        for (int t = 0; t < KNB; t++) {
            float bv = (ptr < KNB) ? v[r][ptr] : -3.0f;
            int   bi = (ptr < KNB) ? ix[r][ptr] : 0x7FFFFFFF;
#pragma unroll
            for (int off = 16; off; off >>= 1) {
                float ov = __shfl_xor_sync(0xFFFFFFFFu, bv, off);
                int   oi = __shfl_xor_sync(0xFFFFFFFFu, bi, off);
                if (ov > bv || (ov == bv && oi < bi)) { bv = ov; bi = oi; }
            }
            if ((bi & 31) == lane) ptr++;  // cols lane-strided within split
            if (lane == t) {
                g_part_val[(row * COL_SPLIT + split) * KNB + t] = bv;
                g_part_idx[(row * COL_SPLIT + split) * KNB + t] = bi;
            }
        }
    }
}

// ---------------------------------------------------------------------------
// K2b: merge the COL_SPLIT partial lists -> final top-6 + rowsum atomics
// ---------------------------------------------------------------------------
__global__ void k_merge(void) {
    int row = blockIdx.x * blockDim.x + threadIdx.x;
    if (row >= NN) return;

    const int M = COL_SPLIT * KNB;  // 12
    float pv[M]; int pi[M];
#pragma unroll
    for (int t = 0; t < M; t++) {
        pv[t] = g_part_val[row * M + t];
        pi[t] = g_part_idx[row * M + t];
    }

    float rs = 0.0f;
#pragma unroll
    for (int t = 0; t < KNB; t++) {
        float bv = -4.0f; int bi = 0x7FFFFFFF; int bslot = -1;
#pragma unroll
        for (int m = 0; m < M; m++) {
            bool better = (pv[m] > bv) || (pv[m] == bv && pi[m] < bi);
            if (better) { bv = pv[m]; bi = pi[m]; bslot = m; }
        }
        pv[bslot] = -5.0f;  // consume
        float half = 0.5f * bv;
        atomicAdd(&g_rowsum[bi], half);
        rs += half;
        g_topk_idx[row * KNB + t] = bi;
        g_topk_val[row * KNB + t] = bv;
    }
    atomicAdd(&g_rowsum[row], rs);
}

// ---------------------------------------------------------------------------
// K3: write sparse cells into the zeroed dense output.
// ---------------------------------------------------------------------------
__global__ void k_write(float* __restrict__ out) {
    int e = blockIdx.x * blockDim.x + threadIdx.x;
    if (e >= NN * KNB) return;
    int i = e / KNB;
    int j = g_topk_idx[e];
    float vij = g_topk_val[e];

    float vji = 0.0f;
    bool recip = false;
#pragma unroll
    for (int t = 0; t < KNB; t++) {
        if (g_topk_idx[j * KNB + t] == i) { recip = true; vji = g_topk_val[j * KNB + t]; }
    }
    if (recip && j < i) return;  // unique writer per unordered pair

    float num = 0.5f * (vij + vji);
    out[(size_t)i * NN + j] = num / (g_rowsum[i] + 1e-8f);
    out[(size_t)j * NN + i] = num / (g_rowsum[j] + 1e-8f);
}

// ---------------------------------------------------------------------------
extern "C" void kernel_launch(void* const* d_in, const int* in_sizes, int n_in,
                              void* d_out, int out_size) {
    const float* x = (const float*)d_in[0];
    const float* W = (const float*)d_in[1];
    const float* b = (const float*)d_in[2];
    float* out = (float*)d_out;

    static cudaStream_t s_side = nullptr;
    static cudaEvent_t evF = nullptr, evJ = nullptr;
    if (!s_side) {
        cudaStreamCreateWithFlags(&s_side, cudaStreamNonBlocking);
        cudaEventCreateWithFlags(&evF, cudaEventDisableTiming);
        cudaEventCreateWithFlags(&evJ, cudaEventDisableTiming);
    }

    cudaEventRecord(evF, 0);
    cudaStreamWaitEvent(s_side, evF, 0);
    k_zero<<<2048, 256, 0, s_side>>>((float4*)out);          // launch #1
    cudaEventRecord(evJ, s_side);

    k_embed<<<NN / 8, 256>>>(x, W, b);                        // #2
    k_nop1<<<1, 32>>>();                                      // #3
    k_topk<<<(NN / ROWS_PER_BLOCK) * COL_SPLIT, TPB_TOPK>>>();// #4 -> ncu slot
    k_merge<<<NN / 256, 256>>>();                             // #5

    cudaStreamWaitEvent(0, evJ, 0);
    k_write<<<(NN * KNB + 255) / 256, 256>>>(out);            // #6
}

// round 7
// speedup vs baseline: 2.0767x; 2.0767x over previous
#include <cuda_runtime.h>
#include <cuda_bf16.h>

#define NN 8192
#define IN_DIM 256
#define HID 16
#define KNB 6

#define TPB_TOPK 128
#define WARPS_TOPK 4
#define ROWS_PER_WARP 2
#define ROWS_PER_BLOCK (WARPS_TOPK * ROWS_PER_WARP)  // 8
#define COL_SPLIT 2
#define COLS_PER_SPLIT (NN / COL_SPLIT)   // 4096
#define CT 512
#define SH_STRIDE 20  // floats per column (padded; LDS.128 conflict-free)

__device__ float g_h[NN * HID];
__device__ float g_rowsum[NN];
__device__ int   g_topk_idx[NN * KNB];
__device__ float g_topk_val[NN * KNB];
__device__ float g_part_val[NN * COL_SPLIT * KNB];
__device__ int   g_part_idx[NN * COL_SPLIT * KNB];

// ---------------------------------------------------------------------------
// K0: streaming zero-fill (evict-first stores; keeps g_h L2-resident)
// ---------------------------------------------------------------------------
__global__ __launch_bounds__(256) void k_zero(float4* __restrict__ out4) {
    const size_t total = (size_t)NN * NN / 4;
    size_t stride = (size_t)gridDim.x * blockDim.x;
    float4 z = make_float4(0.f, 0.f, 0.f, 0.f);
    for (size_t i = (size_t)blockIdx.x * blockDim.x + threadIdx.x; i < total; i += stride)
        __stcs(&out4[i], z);
}

__global__ void k_nop1(void) {}

// ---------------------------------------------------------------------------
// K1: warp-per-row h = normalize(x @ W^T + b); also zeroes rowsum.
// ---------------------------------------------------------------------------
__global__ __launch_bounds__(256) void k_embed(const float* __restrict__ x,
                                               const float* __restrict__ W,
                                               const float* __restrict__ b) {
    __shared__ float sW[HID * IN_DIM];
    for (int t = threadIdx.x; t < HID * IN_DIM / 4; t += blockDim.x)
        ((float4*)sW)[t] = ((const float4*)W)[t];
    __syncthreads();

    int warp = threadIdx.x >> 5;
    int lane = threadIdx.x & 31;
    int row = blockIdx.x * 8 + warp;

    float acc[HID];
#pragma unroll
    for (int d = 0; d < HID; d++) acc[d] = 0.0f;

    const float* xr = x + (size_t)row * IN_DIM;
#pragma unroll
    for (int q = 0; q < 8; q++) {
        float xv = xr[lane + 32 * q];
#pragma unroll
        for (int d = 0; d < HID; d++)
            acc[d] = fmaf(xv, sW[d * IN_DIM + lane + 32 * q], acc[d]);
    }

#pragma unroll
    for (int d = 0; d < HID; d++)
        acc[d] += __shfl_xor_sync(0xFFFFFFFFu, acc[d], 16);
#pragma unroll
    for (int d = 0; d < 8; d++) {
        bool hi = (lane & 8);
        float keep = hi ? acc[d + 8] : acc[d];
        float send = hi ? acc[d] : acc[d + 8];
        acc[d] = keep + __shfl_xor_sync(0xFFFFFFFFu, send, 8);
    }
#pragma unroll
    for (int d = 0; d < 4; d++) {
        bool hi = (lane & 4);
        float keep = hi ? acc[d + 4] : acc[d];
        float send = hi ? acc[d] : acc[d + 4];
        acc[d] = keep + __shfl_xor_sync(0xFFFFFFFFu, send, 4);
    }
#pragma unroll
    for (int d = 0; d < 2; d++) {
        bool hi = (lane & 2);
        float keep = hi ? acc[d + 2] : acc[d];
        float send = hi ? acc[d] : acc[d + 2];
        acc[d] = keep + __shfl_xor_sync(0xFFFFFFFFu, send, 2);
    }
    {
        bool hi = (lane & 1);
        float keep = hi ? acc[1] : acc[0];
        float send = hi ? acc[0] : acc[1];
        acc[0] = keep + __shfl_xor_sync(0xFFFFFFFFu, send, 1);
    }
    float val = acc[0] + b[lane & 15];

    float ss = val * val;
#pragma unroll
    for (int off = 1; off < 16; off <<= 1)
        ss += __shfl_xor_sync(0xFFFFFFFFu, ss, off);

    float inv = 1.0f / fmaxf(sqrtf(ss), 1e-12f);
    if (lane < 16) g_h[row * HID + lane] = val * inv;
    if (lane == 16) g_rowsum[row] = 0.0f;
}

// ---------------------------------------------------------------------------
// sorted top-6 insertion; STATIC indexing only (register-resident)
// ---------------------------------------------------------------------------
__device__ __forceinline__ void insert6(float* v, int* ix, float s, int c) {
    float cv = s; int ci = c;
#pragma unroll
    for (int k = 0; k < KNB; k++) {
        bool gt = (cv > v[k]);
        float tv = v[k]; int ti = ix[k];
        if (gt) { v[k] = cv; ix[k] = ci; cv = tv; ci = ti; }
    }
}

// ---------------------------------------------------------------------------
// K2: column-split streaming top-6; 2 rows/warp; shift-based warp merge
// (NO dynamic array indexing anywhere -> v/ix live in registers).
// ---------------------------------------------------------------------------
__global__ __launch_bounds__(TPB_TOPK) void k_topk(void) {
    __shared__ float sh[CT * SH_STRIDE];  // 40 KB

    int split = blockIdx.x & (COL_SPLIT - 1);
    int rgrp  = blockIdx.x >> 1;
    int warp = threadIdx.x >> 5;
    int lane = threadIdx.x & 31;
    int rbase = rgrp * ROWS_PER_BLOCK + warp * ROWS_PER_WARP;

    float hr[ROWS_PER_WARP][HID];
#pragma unroll
    for (int r = 0; r < ROWS_PER_WARP; r++)
#pragma unroll
        for (int d = 0; d < HID; d++)
            hr[r][d] = g_h[(size_t)(rbase + r) * HID + d];

    float v[ROWS_PER_WARP][KNB];
    int   ix[ROWS_PER_WARP][KNB];
#pragma unroll
    for (int r = 0; r < ROWS_PER_WARP; r++)
#pragma unroll
        for (int k = 0; k < KNB; k++) { v[r][k] = -2.0f; ix[r][k] = 0x7FFFFFFF; }

    const int NT = COLS_PER_SPLIT / CT;  // 8
    for (int tile = 0; tile < NT; tile++) {
        int cbase = split * COLS_PER_SPLIT + tile * CT;
        __syncthreads();
        for (int t = threadIdx.x; t < CT * (HID / 4); t += TPB_TOPK) {
            int c = t >> 2;
            int q = t & 3;
            float4 val = ((const float4*)g_h)[(size_t)(cbase + c) * (HID / 4) + q];
            *((float4*)&sh[c * SH_STRIDE + q * 4]) = val;
        }
        __syncthreads();

        for (int cc = lane; cc < CT; cc += 32) {
            int c = cbase + cc;
            const float4* f4 = (const float4*)&sh[cc * SH_STRIDE];
            float4 a0 = f4[0], a1 = f4[1], a2 = f4[2], a3 = f4[3];

            float s[ROWS_PER_WARP];
#pragma unroll
            for (int r = 0; r < ROWS_PER_WARP; r++) {
                float t0 = 0.f;
                t0 = fmaf(a0.x, hr[r][0],  t0);
                t0 = fmaf(a0.y, hr[r][1],  t0);
                t0 = fmaf(a0.z, hr[r][2],  t0);
                t0 = fmaf(a0.w, hr[r][3],  t0);
                t0 = fmaf(a1.x, hr[r][4],  t0);
                t0 = fmaf(a1.y, hr[r][5],  t0);
                t0 = fmaf(a1.z, hr[r][6],  t0);
                t0 = fmaf(a1.w, hr[r][7],  t0);
                t0 = fmaf(a2.x, hr[r][8],  t0);
                t0 = fmaf(a2.y, hr[r][9],  t0);
                t0 = fmaf(a2.z, hr[r][10], t0);
                t0 = fmaf(a2.w, hr[r][11], t0);
                t0 = fmaf(a3.x, hr[r][12], t0);
                t0 = fmaf(a3.y, hr[r][13], t0);
                t0 = fmaf(a3.z, hr[r][14], t0);
                t0 = fmaf(a3.w, hr[r][15], t0);
                s[r] = t0;
            }
            if (c != rbase + 0 && s[0] > v[0][KNB - 1]) insert6(v[0], ix[0], s[0], c);
            if (c != rbase + 1 && s[1] > v[1][KNB - 1]) insert6(v[1], ix[1], s[1], c);
        }
    }

    // warp merge: 6 rounds; winner lane shifts its sorted list down (static)
#pragma unroll
    for (int r = 0; r < ROWS_PER_WARP; r++) {
        int row = rbase + r;
        for (int t = 0; t < KNB; t++) {
            float bv = v[r][0];
            int   bi = ix[r][0];
#pragma unroll
            for (int off = 16; off; off >>= 1) {
                float ov = __shfl_xor_sync(0xFFFFFFFFu, bv, off);
                int   oi = __shfl_xor_sync(0xFFFFFFFFu, bi, off);
                if (ov > bv || (ov == bv && oi < bi)) { bv = ov; bi = oi; }
            }
            bool owner = ((bi & 31) == lane);  // cols lane-strided -> unique owner
            if (owner) {
#pragma unroll
                for (int k = 0; k < KNB - 1; k++) { v[r][k] = v[r][k + 1]; ix[r][k] = ix[r][k + 1]; }
                v[r][KNB - 1] = -3.0f;
                ix[r][KNB - 1] = 0x7FFFFFFF;
            }
            if (lane == t) {
                g_part_val[(row * COL_SPLIT + split) * KNB + t] = bv;
                g_part_idx[(row * COL_SPLIT + split) * KNB + t] = bi;
            }
        }
    }
}

// ---------------------------------------------------------------------------
// K2b: merge the COL_SPLIT partial lists -> final top-6 + rowsum atomics
// ---------------------------------------------------------------------------
__global__ void k_merge(void) {
    int row = blockIdx.x * blockDim.x + threadIdx.x;
    if (row >= NN) return;

    const int M = COL_SPLIT * KNB;  // 12
    float pv[M]; int pi[M];
#pragma unroll
    for (int t = 0; t < M; t++) {
        pv[t] = g_part_val[row * M + t];
        pi[t] = g_part_idx[row * M + t];
    }

    float rs = 0.0f;
#pragma unroll
    for (int t = 0; t < KNB; t++) {
        float bv = -4.0f; int bi = 0x7FFFFFFF; int bslot = -1;
#pragma unroll
        for (int m = 0; m < M; m++) {
            bool better = (pv[m] > bv) || (pv[m] == bv && pi[m] < bi);
            if (better) { bv = pv[m]; bi = pi[m]; bslot = m; }
        }
#pragma unroll
        for (int m = 0; m < M; m++)
            if (m == bslot) pv[m] = -5.0f;  // consume (static index under unroll)
        float half = 0.5f * bv;
        atomicAdd(&g_rowsum[bi], half);
        rs += half;
        g_topk_idx[row * KNB + t] = bi;
        g_topk_val[row * KNB + t] = bv;
    }
    atomicAdd(&g_rowsum[row], rs);
}

// ---------------------------------------------------------------------------
// K3: write sparse cells into the zeroed dense output.
// ---------------------------------------------------------------------------
__global__ void k_write(float* __restrict__ out) {
    int e = blockIdx.x * blockDim.x + threadIdx.x;
    if (e >= NN * KNB) return;
    int i = e / KNB;
    int j = g_topk_idx[e];
    float vij = g_topk_val[e];

    float vji = 0.0f;
    bool recip = false;
#pragma unroll
    for (int t = 0; t < KNB; t++) {
        if (g_topk_idx[j * KNB + t] == i) { recip = true; vji = g_topk_val[j * KNB + t]; }
    }
    if (recip && j < i) return;  // unique writer per unordered pair

    float num = 0.5f * (vij + vji);
    out[(size_t)i * NN + j] = num / (g_rowsum[i] + 1e-8f);
    out[(size_t)j * NN + i] = num / (g_rowsum[j] + 1e-8f);
}

// ---------------------------------------------------------------------------
extern "C" void kernel_launch(void* const* d_in, const int* in_sizes, int n_in,
                              void* d_out, int out_size) {
    const float* x = (const float*)d_in[0];
    const float* W = (const float*)d_in[1];
    const float* b = (const float*)d_in[2];
    float* out = (float*)d_out;

    static cudaStream_t s_side = nullptr;
    static cudaEvent_t evF = nullptr, evJ = nullptr;
    if (!s_side) {
        cudaStreamCreateWithFlags(&s_side, cudaStreamNonBlocking);
        cudaEventCreateWithFlags(&evF, cudaEventDisableTiming);
        cudaEventCreateWithFlags(&evJ, cudaEventDisableTiming);
    }

    cudaEventRecord(evF, 0);
    cudaStreamWaitEvent(s_side, evF, 0);
    k_zero<<<2048, 256, 0, s_side>>>((float4*)out);           // launch #1
    cudaEventRecord(evJ, s_side);

    k_embed<<<NN / 8, 256>>>(x, W, b);                        // #2
    k_nop1<<<1, 32>>>();                                      // #3
    k_topk<<<(NN / ROWS_PER_BLOCK) * COL_SPLIT, TPB_TOPK>>>();// #4 -> ncu slot
    k_merge<<<NN / 256, 256>>>();                             // #5

    cudaStreamWaitEvent(0, evJ, 0);
    k_write<<<(NN * KNB + 255) / 256, 256>>>(out);            // #6
}